// round 9
// baseline (speedup 1.0000x reference)
#include <cuda_runtime.h>

typedef unsigned long long u64;

__device__ __forceinline__ u64 pk2(float lo, float hi) {
    u64 r; asm("mov.b64 %0,{%1,%2};" : "=l"(r) : "f"(lo), "f"(hi)); return r;
}
__device__ __forceinline__ float2 up2(u64 v) {
    float2 f; asm("mov.b64 {%0,%1},%2;" : "=f"(f.x), "=f"(f.y) : "l"(v)); return f;
}
__device__ __forceinline__ u64 fma2(u64 a, u64 b, u64 c) {
    u64 d; asm("fma.rn.f32x2 %0,%1,%2,%3;" : "=l"(d) : "l"(a), "l"(b), "l"(c)); return d;
}
__device__ __forceinline__ u64 add2(u64 a, u64 b) {
    u64 d; asm("add.rn.f32x2 %0,%1,%2;" : "=l"(d) : "l"(a), "l"(b)); return d;
}
__device__ __forceinline__ u64 clamp2(u64 v) {
    float2 f = up2(v);
    f.x = fminf(fmaxf(f.x, -1.0f), 1.0f);
    f.y = fminf(fmaxf(f.y, -1.0f), 1.0f);
    return pk2(f.x, f.y);
}

#define NPMAX 65536
// transposed input, interleaved col-pairs: pair cp, sample-pair t ->
//   ulonglong2{ pack(col 2cp, t), pack(col 2cp+1, t) }   (193 col-pairs)
__device__ u64 g_T2[(size_t)2 * 193 * NPMAX];   // 202 MB
// sight scratch: col-pair cp (0..71), t -> ulonglong2{sight[2cp], sight[2cp+1]}
__device__ u64 g_S[(size_t)144 * NPMAX];        // 75.5 MB

// ------------------------- transpose + pack kernel -------------------------
__global__ void transpose_kernel(const float* __restrict__ inp, int np)
{
    __shared__ float tile[64][33];
    int bx = blockIdx.x;            // col tile (0..12): cols bx*32..bx*32+31
    int by = blockIdx.y;            // 64-sample tile
    int tid = threadIdx.x;
    int lx = tid & 31, ly = tid >> 5;
    int col = bx * 32 + lx;

    #pragma unroll
    for (int i = 0; i < 8; i++) {
        int r = ly + i * 8;
        float v = 0.0f;
        if (col < 385) v = inp[(size_t)(by * 64 + r) * 385 + col];
        tile[r][lx] = v;
    }
    __syncthreads();

    int pl = tid & 31;              // sample-pair within tile (0..31)
    int cl = tid >> 5;              // 0..7
    ulonglong2* T2 = reinterpret_cast<ulonglong2*>(g_T2);
    #pragma unroll
    for (int i = 0; i < 2; i++) {
        int cpl = cl + i * 8;       // local col-pair (0..15)
        int c   = cpl * 2;
        int gcp = bx * 16 + cpl;    // global col-pair
        if (gcp < 193) {
            u64 lo = pk2(tile[2 * pl][c],     tile[2 * pl + 1][c]);
            u64 hi = pk2(tile[2 * pl][c + 1], tile[2 * pl + 1][c + 1]);
            T2[(size_t)gcp * np + by * 32 + pl] = make_ulonglong2(lo, hi);
        }
    }
}

// ------------------------------ conv kernel -------------------------------
// smem u64 layout (even offsets -> 16B aligned)
#define A_W1 0      // 648
#define A_B1 648    // 12
#define A_W2 660    // 144
#define A_B2 804    // 12
#define A_W3 816    // 48
#define A_B3 864    // 4
#define A_N  868

__global__ void __launch_bounds__(64, 4) conv_kernel(
    const float* __restrict__ W1, const float* __restrict__ b1,
    const float* __restrict__ W2, const float* __restrict__ b2,
    const float* __restrict__ W3, const float* __restrict__ b3,
    int np)
{
    __shared__ __align__(16) u64 sw[A_N];
    int tid = threadIdx.x;
    for (int i = tid; i < 648; i += 64) { float v = W1[i]; sw[A_W1+i] = pk2(v,v); }
    for (int i = tid; i < 12;  i += 64) { sw[A_B1+i] = pk2(b1[i],b1[i]);
                                          sw[A_B2+i] = pk2(b2[i],b2[i]); }
    for (int i = tid; i < 144; i += 64) { sw[A_W2+i] = pk2(W2[i],W2[i]); }
    for (int i = tid; i < 48;  i += 64) { sw[A_W3+i] = pk2(W3[i],W3[i]); }
    if (tid < 4) sw[A_B3+tid] = pk2(b3[tid],b3[tid]);
    __syncthreads();

    int nh = np >> 1;
    int u = blockIdx.x * 64 + tid;
    if (u >= nh) return;
    int t0 = u, t1 = u + nh;

    const ulonglong2* T2 = reinterpret_cast<const ulonglong2*>(g_T2);
    ulonglong2* S = reinterpret_cast<ulonglong2*>(g_S);

    #pragma unroll 1
    for (int wp = 0; wp < 18; wp++) {
        int x  = wp / 3;
        int yy = (wp - x * 3) * 2;
        int cpb = (x * 48 + yy * 6) >> 1;   // col-pair base (cols are even)

        // hA/hB: windows (x,yy),(x,yy+1) of pack0; hC/hD: same for pack1
        u64 hA[12], hB[12], hC[12], hD[12];
        #pragma unroll
        for (int n = 0; n < 12; n++) {
            u64 b = sw[A_B1 + n]; hA[n]=b; hB[n]=b; hC[n]=b; hD[n]=b;
        }

        #pragma unroll 1
        for (int ox = 0; ox < 3; ox++) {
            const ulonglong2* g0 = T2 + (size_t)(cpb + ox * 24) * np + t0;
            const ulonglong2* g1 = T2 + (size_t)(cpb + ox * 24) * np + t1;
            const u64* wk = sw + A_W1 + ox * 216;

            u64 v0[12], v1[12];
            #pragma unroll
            for (int i = 0; i < 6; i++) {
                ulonglong2 a = __ldg(g0 + (size_t)i * np);
                ulonglong2 b = __ldg(g1 + (size_t)i * np);
                v0[2*i] = a.x; v0[2*i+1] = a.y;
                v1[2*i] = b.x; v1[2*i+1] = b.y;
            }
            // phase 0: k = 0..5
            #pragma unroll
            for (int kk = 0; kk < 6; kk++) {
                u64 a0 = v0[kk], b0 = v0[kk+6], a1 = v1[kk], b1v = v1[kk+6];
                const ulonglong2* w2 = reinterpret_cast<const ulonglong2*>(wk + kk * 12);
                #pragma unroll
                for (int n2 = 0; n2 < 6; n2++) {
                    ulonglong2 w = w2[n2];
                    hA[2*n2]=fma2(a0,w.x,hA[2*n2]);   hA[2*n2+1]=fma2(a0,w.y,hA[2*n2+1]);
                    hB[2*n2]=fma2(b0,w.x,hB[2*n2]);   hB[2*n2+1]=fma2(b0,w.y,hB[2*n2+1]);
                    hC[2*n2]=fma2(a1,w.x,hC[2*n2]);   hC[2*n2+1]=fma2(a1,w.y,hC[2*n2+1]);
                    hD[2*n2]=fma2(b1v,w.x,hD[2*n2]);  hD[2*n2+1]=fma2(b1v,w.y,hD[2*n2+1]);
                }
            }
            // phase 1: k = 6..11 (cols 12..17 = pairs 6..8)
            #pragma unroll
            for (int i = 0; i < 6; i++) { v0[i]=v0[i+6]; v1[i]=v1[i+6]; }
            #pragma unroll
            for (int i = 0; i < 3; i++) {
                ulonglong2 a = __ldg(g0 + (size_t)(6+i) * np);
                ulonglong2 b = __ldg(g1 + (size_t)(6+i) * np);
                v0[6+2*i]=a.x; v0[7+2*i]=a.y; v1[6+2*i]=b.x; v1[7+2*i]=b.y;
            }
            #pragma unroll
            for (int kk = 0; kk < 6; kk++) {
                u64 a0 = v0[kk], b0 = v0[kk+6], a1 = v1[kk], b1v = v1[kk+6];
                const ulonglong2* w2 = reinterpret_cast<const ulonglong2*>(wk + (6+kk) * 12);
                #pragma unroll
                for (int n2 = 0; n2 < 6; n2++) {
                    ulonglong2 w = w2[n2];
                    hA[2*n2]=fma2(a0,w.x,hA[2*n2]);   hA[2*n2+1]=fma2(a0,w.y,hA[2*n2+1]);
                    hB[2*n2]=fma2(b0,w.x,hB[2*n2]);   hB[2*n2+1]=fma2(b0,w.y,hB[2*n2+1]);
                    hC[2*n2]=fma2(a1,w.x,hC[2*n2]);   hC[2*n2+1]=fma2(a1,w.y,hC[2*n2+1]);
                    hD[2*n2]=fma2(b1v,w.x,hD[2*n2]);  hD[2*n2+1]=fma2(b1v,w.y,hD[2*n2+1]);
                }
            }
            // phase 2: k = 12..17 (cols 18..23 = pairs 9..11)
            #pragma unroll
            for (int i = 0; i < 6; i++) { v0[i]=v0[i+6]; v1[i]=v1[i+6]; }
            #pragma unroll
            for (int i = 0; i < 3; i++) {
                ulonglong2 a = __ldg(g0 + (size_t)(9+i) * np);
                ulonglong2 b = __ldg(g1 + (size_t)(9+i) * np);
                v0[6+2*i]=a.x; v0[7+2*i]=a.y; v1[6+2*i]=b.x; v1[7+2*i]=b.y;
            }
            #pragma unroll
            for (int kk = 0; kk < 6; kk++) {
                u64 a0 = v0[kk], b0 = v0[kk+6], a1 = v1[kk], b1v = v1[kk+6];
                const ulonglong2* w2 = reinterpret_cast<const ulonglong2*>(wk + (12+kk) * 12);
                #pragma unroll
                for (int n2 = 0; n2 < 6; n2++) {
                    ulonglong2 w = w2[n2];
                    hA[2*n2]=fma2(a0,w.x,hA[2*n2]);   hA[2*n2+1]=fma2(a0,w.y,hA[2*n2+1]);
                    hB[2*n2]=fma2(b0,w.x,hB[2*n2]);   hB[2*n2+1]=fma2(b0,w.y,hB[2*n2+1]);
                    hC[2*n2]=fma2(a1,w.x,hC[2*n2]);   hC[2*n2+1]=fma2(a1,w.y,hC[2*n2+1]);
                    hD[2*n2]=fma2(b1v,w.x,hD[2*n2]);  hD[2*n2+1]=fma2(b1v,w.y,hD[2*n2+1]);
                }
            }
        }
        #pragma unroll
        for (int n = 0; n < 12; n++) {
            hA[n]=clamp2(hA[n]); hB[n]=clamp2(hB[n]);
            hC[n]=clamp2(hC[n]); hD[n]=clamp2(hD[n]);
        }

        int wa = x * 6 + yy;
        size_t base = (size_t)(2 * wa) * np;

        // ---- pack0: L2 + L3 + store (keeps hC/hD live, bounds registers) ----
        {
            u64 gA[12], gB[12];
            #pragma unroll
            for (int n = 0; n < 12; n++) { u64 b = sw[A_B2+n]; gA[n]=b; gB[n]=b; }
            #pragma unroll 4
            for (int k = 0; k < 12; k++) {
                const ulonglong2* w2 = reinterpret_cast<const ulonglong2*>(sw + A_W2 + k*12);
                #pragma unroll
                for (int n2 = 0; n2 < 6; n2++) {
                    ulonglong2 w = w2[n2];
                    gA[2*n2]=fma2(hA[k],w.x,gA[2*n2]);  gA[2*n2+1]=fma2(hA[k],w.y,gA[2*n2+1]);
                    gB[2*n2]=fma2(hB[k],w.x,gB[2*n2]);  gB[2*n2+1]=fma2(hB[k],w.y,gB[2*n2+1]);
                }
            }
            #pragma unroll
            for (int n = 0; n < 12; n++) { gA[n]=clamp2(gA[n]); gB[n]=clamp2(gB[n]); }

            u64 sA[4], sB[4];
            #pragma unroll
            for (int q = 0; q < 4; q++) { u64 b = sw[A_B3+q]; sA[q]=b; sB[q]=b; }
            #pragma unroll
            for (int k = 0; k < 12; k++) {
                const ulonglong2* w2 = reinterpret_cast<const ulonglong2*>(sw + A_W3 + k*4);
                #pragma unroll
                for (int q2 = 0; q2 < 2; q2++) {
                    ulonglong2 w = w2[q2];
                    sA[2*q2]=fma2(gA[k],w.x,sA[2*q2]);  sA[2*q2+1]=fma2(gA[k],w.y,sA[2*q2+1]);
                    sB[2*q2]=fma2(gB[k],w.x,sB[2*q2]);  sB[2*q2+1]=fma2(gB[k],w.y,sB[2*q2+1]);
                }
            }
            #pragma unroll
            for (int q = 0; q < 4; q++) { sA[q]=clamp2(sA[q]); sB[q]=clamp2(sB[q]); }

            S[base            + t0] = make_ulonglong2(sA[0], sA[1]);
            S[base +     np   + t0] = make_ulonglong2(sA[2], sA[3]);
            S[base + 2 * (size_t)np + t0] = make_ulonglong2(sB[0], sB[1]);
            S[base + 3 * (size_t)np + t0] = make_ulonglong2(sB[2], sB[3]);
        }
        // ---- pack1 ----
        {
            u64 gC[12], gD[12];
            #pragma unroll
            for (int n = 0; n < 12; n++) { u64 b = sw[A_B2+n]; gC[n]=b; gD[n]=b; }
            #pragma unroll 4
            for (int k = 0; k < 12; k++) {
                const ulonglong2* w2 = reinterpret_cast<const ulonglong2*>(sw + A_W2 + k*12);
                #pragma unroll
                for (int n2 = 0; n2 < 6; n2++) {
                    ulonglong2 w = w2[n2];
                    gC[2*n2]=fma2(hC[k],w.x,gC[2*n2]);  gC[2*n2+1]=fma2(hC[k],w.y,gC[2*n2+1]);
                    gD[2*n2]=fma2(hD[k],w.x,gD[2*n2]);  gD[2*n2+1]=fma2(hD[k],w.y,gD[2*n2+1]);
                }
            }
            #pragma unroll
            for (int n = 0; n < 12; n++) { gC[n]=clamp2(gC[n]); gD[n]=clamp2(gD[n]); }

            u64 sC[4], sD[4];
            #pragma unroll
            for (int q = 0; q < 4; q++) { u64 b = sw[A_B3+q]; sC[q]=b; sD[q]=b; }
            #pragma unroll
            for (int k = 0; k < 12; k++) {
                const ulonglong2* w2 = reinterpret_cast<const ulonglong2*>(sw + A_W3 + k*4);
                #pragma unroll
                for (int q2 = 0; q2 < 2; q2++) {
                    ulonglong2 w = w2[q2];
                    sC[2*q2]=fma2(gC[k],w.x,sC[2*q2]);  sC[2*q2+1]=fma2(gC[k],w.y,sC[2*q2+1]);
                    sD[2*q2]=fma2(gD[k],w.x,sD[2*q2]);  sD[2*q2+1]=fma2(gD[k],w.y,sD[2*q2+1]);
                }
            }
            #pragma unroll
            for (int q = 0; q < 4; q++) { sC[q]=clamp2(sC[q]); sD[q]=clamp2(sD[q]); }

            S[base            + t1] = make_ulonglong2(sC[0], sC[1]);
            S[base +     np   + t1] = make_ulonglong2(sC[2], sC[3]);
            S[base + 2 * (size_t)np + t1] = make_ulonglong2(sD[0], sD[1]);
            S[base + 3 * (size_t)np + t1] = make_ulonglong2(sD[2], sD[3]);
        }
    }
}

// ------------------------------ head kernel -------------------------------
#define H_V1 0      // 4640 (145x32 pairs)
#define H_C1 4640   // 32
#define H_C2 4672   // 32
#define H_V3 4704   // 32
#define H_V2 4736   // 1024 (V2 transposed pairs: [j][k])
#define H_C3 5760   // 1 (+1 pad)
#define H_N  5762   // 46096 B

__global__ void __launch_bounds__(128, 2) head_kernel(
    const float* __restrict__ V1, const float* __restrict__ c1,
    const float* __restrict__ V2, const float* __restrict__ c2,
    const float* __restrict__ V3, const float* __restrict__ c3,
    float* __restrict__ out, int np)
{
    __shared__ __align__(16) u64 sv[H_N];
    int tid = threadIdx.x;
    for (int i = tid; i < 4640; i += 128) { float v = V1[i]; sv[H_V1+i] = pk2(v,v); }
    for (int i = tid; i < 32;   i += 128) { sv[H_C1+i] = pk2(c1[i],c1[i]);
                                            sv[H_C2+i] = pk2(c2[i],c2[i]);
                                            sv[H_V3+i] = pk2(V3[i],V3[i]); }
    for (int i = tid; i < 1024; i += 128) { int j = i >> 5, k = i & 31;
                                            float v = V2[k*32 + j]; sv[H_V2+i] = pk2(v,v); }
    if (tid == 0) sv[H_C3] = pk2(c3[0], c3[0]);
    __syncthreads();

    int nh = np >> 1;
    int u = blockIdx.x * 128 + tid;
    if (u >= nh) return;
    int t0 = u, t1 = u + nh;

    const ulonglong2* S = reinterpret_cast<const ulonglong2*>(g_S);

    u64 acc0[32], acc1[32];
    #pragma unroll
    for (int j = 0; j < 32; j++) { acc0[j] = 0ull; acc1[j] = 0ull; }

    #pragma unroll 1
    for (int cp = 0; cp < 72; cp++) {
        ulonglong2 s0 = __ldg(S + (size_t)cp * np + t0);
        ulonglong2 s1 = __ldg(S + (size_t)cp * np + t1);
        const ulonglong2* wk0 = reinterpret_cast<const ulonglong2*>(sv + H_V1 + (2*cp)   * 32);
        const ulonglong2* wk1 = reinterpret_cast<const ulonglong2*>(sv + H_V1 + (2*cp+1) * 32);
        #pragma unroll
        for (int j2 = 0; j2 < 16; j2++) {
            ulonglong2 wA = wk0[j2];
            ulonglong2 wB = wk1[j2];
            acc0[2*j2]   = fma2(s0.x, wA.x, acc0[2*j2]);
            acc0[2*j2]   = fma2(s0.y, wB.x, acc0[2*j2]);
            acc0[2*j2+1] = fma2(s0.x, wA.y, acc0[2*j2+1]);
            acc0[2*j2+1] = fma2(s0.y, wB.y, acc0[2*j2+1]);
            acc1[2*j2]   = fma2(s1.x, wA.x, acc1[2*j2]);
            acc1[2*j2]   = fma2(s1.y, wB.x, acc1[2*j2]);
            acc1[2*j2+1] = fma2(s1.x, wA.y, acc1[2*j2+1]);
            acc1[2*j2+1] = fma2(s1.y, wB.y, acc1[2*j2+1]);
        }
    }

    // vision[144] = inp[:,384] (col-pair 192, low half)
    u64 l0 = g_T2[((size_t)192 * np + t0) * 2];
    u64 l1 = g_T2[((size_t)192 * np + t1) * 2];
    const u64* v1l = sv + H_V1 + 144 * 32;
    #pragma unroll
    for (int j = 0; j < 32; j++) {
        acc0[j] = clamp2(add2(fma2(l0, v1l[j], acc0[j]), sv[H_C1 + j]));
        acc1[j] = clamp2(add2(fma2(l1, v1l[j], acc1[j]), sv[H_C1 + j]));
    }

    // V2 (32->32) + V3 (32->1) fused; V2 stored transposed as pairs
    u64 o0 = sv[H_C3], o1 = o0;
    #pragma unroll 1
    for (int j = 0; j < 32; j++) {
        u64 e0 = sv[H_C2 + j], e1 = e0;
        const ulonglong2* w2 = reinterpret_cast<const ulonglong2*>(sv + H_V2 + j * 32);
        #pragma unroll
        for (int k2 = 0; k2 < 16; k2++) {
            ulonglong2 w = w2[k2];
            e0 = fma2(acc0[2*k2], w.x, e0);
            e0 = fma2(acc0[2*k2+1], w.y, e0);
            e1 = fma2(acc1[2*k2], w.x, e1);
            e1 = fma2(acc1[2*k2+1], w.y, e1);
        }
        e0 = clamp2(e0); e1 = clamp2(e1);
        u64 vv = sv[H_V3 + j];
        o0 = fma2(e0, vv, o0);
        o1 = fma2(e1, vv, o1);
    }
    o0 = clamp2(o0); o1 = clamp2(o1);

    reinterpret_cast<float2*>(out)[t0] = up2(o0);
    reinterpret_cast<float2*>(out)[t1] = up2(o1);
}

extern "C" void kernel_launch(void* const* d_in, const int* in_sizes, int n_in,
                              void* d_out, int out_size) {
    const float* inp = (const float*)d_in[0];
    const float* W1  = (const float*)d_in[1];
    const float* b1  = (const float*)d_in[2];
    const float* W2  = (const float*)d_in[3];
    const float* b2  = (const float*)d_in[4];
    const float* W3  = (const float*)d_in[5];
    const float* b3  = (const float*)d_in[6];
    const float* V1  = (const float*)d_in[7];
    const float* c1  = (const float*)d_in[8];
    const float* V2  = (const float*)d_in[9];
    const float* c2  = (const float*)d_in[10];
    const float* V3  = (const float*)d_in[11];
    const float* c3  = (const float*)d_in[12];

    int B  = in_sizes[0] / 385;   // 131072
    int np = B / 2;               // 65536 sample-pairs
    int nh = np / 2;              // 32768 threads in conv/head

    // 1) transpose + pack into interleaved col-pairs
    dim3 tgrid(13, B / 64);
    transpose_kernel<<<tgrid, 256>>>(inp, np);

    // 2) conv: windows -> sight (4 samples per thread)
    conv_kernel<<<(nh + 63) / 64, 64>>>(W1, b1, W2, b2, W3, b3, np);

    // 3) head: sight -> output (4 samples per thread)
    head_kernel<<<(nh + 127) / 128, 128>>>(V1, c1, V2, c2, V3, c3,
                                           (float*)d_out, np);
}

// round 10
// speedup vs baseline: 1.1375x; 1.1375x over previous
#include <cuda_runtime.h>

typedef unsigned long long u64;

__device__ __forceinline__ u64 pk2(float lo, float hi) {
    u64 r; asm("mov.b64 %0,{%1,%2};" : "=l"(r) : "f"(lo), "f"(hi)); return r;
}
__device__ __forceinline__ float2 up2(u64 v) {
    float2 f; asm("mov.b64 {%0,%1},%2;" : "=f"(f.x), "=f"(f.y) : "l"(v)); return f;
}
__device__ __forceinline__ u64 fma2(u64 a, u64 b, u64 c) {
    u64 d; asm("fma.rn.f32x2 %0,%1,%2,%3;" : "=l"(d) : "l"(a), "l"(b), "l"(c)); return d;
}
__device__ __forceinline__ u64 add2(u64 a, u64 b) {
    u64 d; asm("add.rn.f32x2 %0,%1,%2;" : "=l"(d) : "l"(a), "l"(b)); return d;
}
__device__ __forceinline__ u64 clamp2(u64 v) {
    float2 f = up2(v);
    f.x = fminf(fmaxf(f.x, -1.0f), 1.0f);
    f.y = fminf(fmaxf(f.y, -1.0f), 1.0f);
    return pk2(f.x, f.y);
}

#define NPMAX 65536
// transposed, sample-pair-packed input: g_T[c][t] = {inp[2t][c], inp[2t+1][c]}
__device__ u64 g_T[385u * NPMAX];          // 201.85 MB
// sight scratch: ulonglong2 row cp (0..71): {sight[2cp] pair, sight[2cp+1] pair}
__device__ u64 g_S[(size_t)144 * NPMAX];   // 75.5 MB

// ------------------------- transpose + pack kernel -------------------------
__global__ void transpose_kernel(const float* __restrict__ inp, int np)
{
    __shared__ float tile[64][33];
    int bx = blockIdx.x;            // col tile (0..12)
    int by = blockIdx.y;            // 64-sample tile
    int tid = threadIdx.x;
    int lx = tid & 31, ly = tid >> 5;
    int col = bx * 32 + lx;

    #pragma unroll
    for (int i = 0; i < 8; i++) {
        int r = ly + i * 8;
        float v = 0.0f;
        if (col < 385) v = inp[(size_t)(by * 64 + r) * 385 + col];
        tile[r][lx] = v;
    }
    __syncthreads();

    int pl = tid & 31;
    int cl = tid >> 5;
    #pragma unroll
    for (int i = 0; i < 4; i++) {
        int c  = cl + i * 8;
        int gc = bx * 32 + c;
        if (gc < 385) {
            u64 v = pk2(tile[2 * pl][c], tile[2 * pl + 1][c]);
            g_T[(size_t)gc * np + by * 32 + pl] = v;
        }
    }
}

// ------------------------------ conv kernel -------------------------------
#define A_W1 0      // 648
#define A_B1 648    // 12
#define A_W2 660    // 144
#define A_B2 804    // 12
#define A_W3 816    // 48
#define A_B3 864    // 4
#define A_N  868

__global__ void __launch_bounds__(128, 4) conv_kernel(
    const float* __restrict__ W1, const float* __restrict__ b1,
    const float* __restrict__ W2, const float* __restrict__ b2,
    const float* __restrict__ W3, const float* __restrict__ b3,
    int np)
{
    __shared__ __align__(16) u64 sw[A_N];
    int tid = threadIdx.x;
    for (int i = tid; i < 648; i += 128) { float v = W1[i]; sw[A_W1+i] = pk2(v,v); }
    for (int i = tid; i < 12;  i += 128) { sw[A_B1+i] = pk2(b1[i],b1[i]);
                                           sw[A_B2+i] = pk2(b2[i],b2[i]); }
    for (int i = tid; i < 144; i += 128) { sw[A_W2+i] = pk2(W2[i],W2[i]); }
    for (int i = tid; i < 48;  i += 128) { sw[A_W3+i] = pk2(W3[i],W3[i]); }
    if (tid < 4) sw[A_B3+tid] = pk2(b3[tid],b3[tid]);
    __syncthreads();

    int t = blockIdx.x * 128 + tid;
    if (t >= np) return;

    ulonglong2* S = reinterpret_cast<ulonglong2*>(g_S);

    #pragma unroll 1
    for (int wp = 0; wp < 18; wp++) {
        int x  = wp / 3;
        int yy = (wp - x * 3) * 2;
        int cbase = x * 48 + yy * 6;

        u64 ha[12], hb[12];
        #pragma unroll
        for (int n = 0; n < 12; n++) { ha[n] = sw[A_B1 + n]; hb[n] = ha[n]; }

        #pragma unroll 1
        for (int ox = 0; ox < 3; ox++) {
            const u64* gcol = g_T + (size_t)(cbase + ox * 48) * np + t;
            const u64* wk = sw + A_W1 + ox * 216;

            u64 v[12];
            #pragma unroll
            for (int i = 0; i < 12; i++) v[i] = __ldg(gcol + (size_t)i * np);

            #pragma unroll
            for (int kk = 0; kk < 6; kk++) {
                u64 va = v[kk], vb = v[kk + 6];
                const ulonglong2* w2 = reinterpret_cast<const ulonglong2*>(wk + kk * 12);
                #pragma unroll
                for (int n2 = 0; n2 < 6; n2++) {
                    ulonglong2 w = w2[n2];
                    ha[2*n2]   = fma2(va, w.x, ha[2*n2]);
                    ha[2*n2+1] = fma2(va, w.y, ha[2*n2+1]);
                    hb[2*n2]   = fma2(vb, w.x, hb[2*n2]);
                    hb[2*n2+1] = fma2(vb, w.y, hb[2*n2+1]);
                }
            }
            #pragma unroll
            for (int i = 0; i < 6; i++) v[i] = v[i + 6];
            #pragma unroll
            for (int i = 0; i < 6; i++) v[6 + i] = __ldg(gcol + (size_t)(12 + i) * np);
            #pragma unroll
            for (int kk = 0; kk < 6; kk++) {
                u64 va = v[kk], vb = v[kk + 6];
                const ulonglong2* w2 = reinterpret_cast<const ulonglong2*>(wk + (6 + kk) * 12);
                #pragma unroll
                for (int n2 = 0; n2 < 6; n2++) {
                    ulonglong2 w = w2[n2];
                    ha[2*n2]   = fma2(va, w.x, ha[2*n2]);
                    ha[2*n2+1] = fma2(va, w.y, ha[2*n2+1]);
                    hb[2*n2]   = fma2(vb, w.x, hb[2*n2]);
                    hb[2*n2+1] = fma2(vb, w.y, hb[2*n2+1]);
                }
            }
            #pragma unroll
            for (int i = 0; i < 6; i++) v[i] = v[i + 6];
            #pragma unroll
            for (int i = 0; i < 6; i++) v[6 + i] = __ldg(gcol + (size_t)(18 + i) * np);
            #pragma unroll
            for (int kk = 0; kk < 6; kk++) {
                u64 va = v[kk], vb = v[kk + 6];
                const ulonglong2* w2 = reinterpret_cast<const ulonglong2*>(wk + (12 + kk) * 12);
                #pragma unroll
                for (int n2 = 0; n2 < 6; n2++) {
                    ulonglong2 w = w2[n2];
                    ha[2*n2]   = fma2(va, w.x, ha[2*n2]);
                    ha[2*n2+1] = fma2(va, w.y, ha[2*n2+1]);
                    hb[2*n2]   = fma2(vb, w.x, hb[2*n2]);
                    hb[2*n2+1] = fma2(vb, w.y, hb[2*n2+1]);
                }
            }
        }
        #pragma unroll
        for (int n = 0; n < 12; n++) { ha[n] = clamp2(ha[n]); hb[n] = clamp2(hb[n]); }

        // layer 2: 12 -> 12
        u64 ga[12], gb[12];
        #pragma unroll
        for (int n = 0; n < 12; n++) { ga[n] = sw[A_B2 + n]; gb[n] = ga[n]; }
        #pragma unroll 4
        for (int k = 0; k < 12; k++) {
            const ulonglong2* w2 = reinterpret_cast<const ulonglong2*>(sw + A_W2 + k * 12);
            #pragma unroll
            for (int n2 = 0; n2 < 6; n2++) {
                ulonglong2 w = w2[n2];
                ga[2*n2]   = fma2(ha[k], w.x, ga[2*n2]);
                ga[2*n2+1] = fma2(ha[k], w.y, ga[2*n2+1]);
                gb[2*n2]   = fma2(hb[k], w.x, gb[2*n2]);
                gb[2*n2+1] = fma2(hb[k], w.y, gb[2*n2+1]);
            }
        }
        #pragma unroll
        for (int n = 0; n < 12; n++) { ga[n] = clamp2(ga[n]); gb[n] = clamp2(gb[n]); }

        // layer 3: 12 -> 4
        u64 sa[4], sb[4];
        #pragma unroll
        for (int q = 0; q < 4; q++) { sa[q] = sw[A_B3 + q]; sb[q] = sa[q]; }
        #pragma unroll
        for (int k = 0; k < 12; k++) {
            const ulonglong2* w2 = reinterpret_cast<const ulonglong2*>(sw + A_W3 + k * 4);
            #pragma unroll
            for (int q2 = 0; q2 < 2; q2++) {
                ulonglong2 w = w2[q2];
                sa[2*q2]   = fma2(ga[k], w.x, sa[2*q2]);
                sa[2*q2+1] = fma2(ga[k], w.y, sa[2*q2+1]);
                sb[2*q2]   = fma2(gb[k], w.x, sb[2*q2]);
                sb[2*q2+1] = fma2(gb[k], w.y, sb[2*q2+1]);
            }
        }
        #pragma unroll
        for (int q = 0; q < 4; q++) { sa[q] = clamp2(sa[q]); sb[q] = clamp2(sb[q]); }

        // store sight pairs (rows 2wa..2wa+3 of ulonglong2-rows)
        int wa = x * 6 + yy;
        size_t base = (size_t)(2 * wa) * np + t;
        S[base                  ] = make_ulonglong2(sa[0], sa[1]);
        S[base +     (size_t)np ] = make_ulonglong2(sa[2], sa[3]);
        S[base + 2 * (size_t)np ] = make_ulonglong2(sb[0], sb[1]);
        S[base + 3 * (size_t)np ] = make_ulonglong2(sb[2], sb[3]);
    }
}

// ------------------------------ head kernel -------------------------------
#define H_V1 0      // 4640 (145x32 dup pairs)
#define H_C1 4640   // 32
#define H_C2 4672   // 32
#define H_V3 4704   // 32
#define H_V2 4736   // 1024 (V2 transposed dup pairs: [j][k])
#define H_C3 5760   // 1 (+1 pad)
#define H_N  5762   // 46096 B

__global__ void __launch_bounds__(128, 4) head_kernel(
    const float* __restrict__ V1, const float* __restrict__ c1,
    const float* __restrict__ V2, const float* __restrict__ c2,
    const float* __restrict__ V3, const float* __restrict__ c3,
    float* __restrict__ out, int np)
{
    __shared__ __align__(16) u64 sv[H_N];
    int tid = threadIdx.x;
    for (int i = tid; i < 4640; i += 128) { float v = V1[i]; sv[H_V1+i] = pk2(v,v); }
    for (int i = tid; i < 32;   i += 128) { sv[H_C1+i] = pk2(c1[i],c1[i]);
                                            sv[H_C2+i] = pk2(c2[i],c2[i]);
                                            sv[H_V3+i] = pk2(V3[i],V3[i]); }
    for (int i = tid; i < 1024; i += 128) { int j = i >> 5, k = i & 31;
                                            float v = V2[k*32 + j]; sv[H_V2+i] = pk2(v,v); }
    if (tid == 0) sv[H_C3] = pk2(c3[0], c3[0]);
    __syncthreads();

    int t = blockIdx.x * 128 + tid;
    if (t >= np) return;

    const ulonglong2* S = reinterpret_cast<const ulonglong2*>(g_S);

    u64 acc[32];
    #pragma unroll
    for (int j = 0; j < 32; j++) acc[j] = 0ull;

    #pragma unroll 2
    for (int cp = 0; cp < 72; cp++) {
        ulonglong2 s = __ldg(S + (size_t)cp * np + t);
        const ulonglong2* wk0 = reinterpret_cast<const ulonglong2*>(sv + H_V1 + (2*cp)   * 32);
        const ulonglong2* wk1 = reinterpret_cast<const ulonglong2*>(sv + H_V1 + (2*cp+1) * 32);
        #pragma unroll
        for (int j2 = 0; j2 < 16; j2++) {
            ulonglong2 wA = wk0[j2];
            ulonglong2 wB = wk1[j2];
            acc[2*j2]   = fma2(s.x, wA.x, acc[2*j2]);
            acc[2*j2]   = fma2(s.y, wB.x, acc[2*j2]);
            acc[2*j2+1] = fma2(s.x, wA.y, acc[2*j2+1]);
            acc[2*j2+1] = fma2(s.y, wB.y, acc[2*j2+1]);
        }
    }

    // vision[144] = inp[:,384]
    u64 last = __ldg(g_T + (size_t)384 * np + t);
    const u64* v1l = sv + H_V1 + 144 * 32;
    #pragma unroll
    for (int j = 0; j < 32; j++) {
        acc[j] = clamp2(add2(fma2(last, v1l[j], acc[j]), sv[H_C1 + j]));
    }

    // V2 (32->32) + V3 (32->1) fused; V2 stored transposed dup'd pairs
    u64 o = sv[H_C3];
    #pragma unroll 1
    for (int j = 0; j < 32; j++) {
        u64 e = sv[H_C2 + j];
        const ulonglong2* w2 = reinterpret_cast<const ulonglong2*>(sv + H_V2 + j * 32);
        #pragma unroll
        for (int k2 = 0; k2 < 16; k2++) {
            ulonglong2 w = w2[k2];
            e = fma2(acc[2*k2],   w.x, e);
            e = fma2(acc[2*k2+1], w.y, e);
        }
        e = clamp2(e);
        o = fma2(e, sv[H_V3 + j], o);
    }
    o = clamp2(o);

    reinterpret_cast<float2*>(out)[t] = up2(o);
}

extern "C" void kernel_launch(void* const* d_in, const int* in_sizes, int n_in,
                              void* d_out, int out_size) {
    const float* inp = (const float*)d_in[0];
    const float* W1  = (const float*)d_in[1];
    const float* b1  = (const float*)d_in[2];
    const float* W2  = (const float*)d_in[3];
    const float* b2  = (const float*)d_in[4];
    const float* W3  = (const float*)d_in[5];
    const float* b3  = (const float*)d_in[6];
    const float* V1  = (const float*)d_in[7];
    const float* c1  = (const float*)d_in[8];
    const float* V2  = (const float*)d_in[9];
    const float* c2  = (const float*)d_in[10];
    const float* V3  = (const float*)d_in[11];
    const float* c3  = (const float*)d_in[12];

    int B  = in_sizes[0] / 385;   // 131072
    int np = B / 2;               // 65536 sample-pairs

    dim3 tgrid(13, B / 64);
    transpose_kernel<<<tgrid, 256>>>(inp, np);

    int blocks = (np + 127) / 128;
    conv_kernel<<<blocks, 128>>>(W1, b1, W2, b2, W3, b3, np);
    head_kernel<<<blocks, 128>>>(V1, c1, V2, c2, V3, c3, (float*)d_out, np);
}